// round 1
// baseline (speedup 1.0000x reference)
#include <cuda_runtime.h>

// ---------------------------------------------------------------------------
// GraphSage (eval) on GB300 — round 1: correct fp32 baseline.
//   h0 = lrelu(emb[ids] @ We^T + be) + lrelu(lrelu(content @ Wp1^T + bp1) @ Wp2^T + bp2)
//   per layer: h_agg = segsum(h[src] by dst)/max(deg,1)
//              hn = [h | h_agg] @ Wc^T + bc  (lrelu if i<L-1), row-L2-normalize
//              if i<L-1: hn = lrelu(hn@Wo1^T+bo1) @ Wo2^T + bo2
// ---------------------------------------------------------------------------

#define NMAX 50000
#define EMAX 1000000
#define FDIM 256
#define NCDIM 300

// static scratch (no allocations allowed)
__device__ __align__(16) float g_h[NMAX * FDIM];
__device__ __align__(16) float g_hn[NMAX * FDIM];
__device__ __align__(16) float g_tmp[NMAX * NCDIM];     // also reused as [N,256]
__device__ __align__(16) float g_hcat[NMAX * 2 * FDIM];
__device__ int g_deg[NMAX];
__device__ int g_rowoff[NMAX + 1];
__device__ int g_cursor[NMAX];
__device__ int g_adj[EMAX];

// ---------------------------------------------------------------------------
__global__ void zero_deg_kernel(int n) {
    int i = blockIdx.x * blockDim.x + threadIdx.x;
    if (i < n) g_deg[i] = 0;
}

__global__ void count_deg_kernel(const int* __restrict__ dst, int E) {
    int i = blockIdx.x * blockDim.x + threadIdx.x;
    int stride = gridDim.x * blockDim.x;
    for (; i < E; i += stride) atomicAdd(&g_deg[dst[i]], 1);
}

// single-block exclusive scan of g_deg -> g_rowoff / g_cursor
__global__ void scan_kernel(int n) {
    __shared__ int warp_sums[32];
    __shared__ int s_carry;
    int t = threadIdx.x;  // 1024 threads
    if (t == 0) s_carry = 0;
    __syncthreads();
    for (int base = 0; base < n; base += 1024) {
        int i = base + t;
        int v = (i < n) ? g_deg[i] : 0;
        // warp inclusive scan
        int x = v;
        #pragma unroll
        for (int off = 1; off < 32; off <<= 1) {
            int y = __shfl_up_sync(0xffffffffu, x, off);
            if ((t & 31) >= off) x += y;
        }
        if ((t & 31) == 31) warp_sums[t >> 5] = x;
        __syncthreads();
        if (t < 32) {
            int w = warp_sums[t];
            int xx = w;
            #pragma unroll
            for (int off = 1; off < 32; off <<= 1) {
                int y = __shfl_up_sync(0xffffffffu, xx, off);
                if (t >= off) xx += y;
            }
            warp_sums[t] = xx - w;  // exclusive warp offset
        }
        __syncthreads();
        int incl = x + warp_sums[t >> 5];
        int excl = incl - v + s_carry;
        if (i < n) { g_rowoff[i] = excl; g_cursor[i] = excl; }
        __syncthreads();
        if (t == 1023) s_carry += incl;   // incl of last thread = tile total
        __syncthreads();
    }
    if (t == 0) g_rowoff[n] = s_carry;
}

__global__ void scatter_kernel(const int* __restrict__ src,
                               const int* __restrict__ dst, int E) {
    int i = blockIdx.x * blockDim.x + threadIdx.x;
    int stride = gridDim.x * blockDim.x;
    for (; i < E; i += stride) {
        int p = atomicAdd(&g_cursor[dst[i]], 1);
        g_adj[p] = src[i];
    }
}

// ---------------------------------------------------------------------------
// aggregate: hcat[n, 0:256] = h[n]; hcat[n, 256:512] = mean over in-neighbors
// blockDim = (64, 4): each warp handles half the feature row of one node;
// actually each y-slice (64 threads = 2 warps) handles one node, thread j owns
// float4 at column 4*j.
__global__ void aggregate_kernel(int N) {
    int node = blockIdx.x * blockDim.y + threadIdx.y;
    if (node >= N) return;
    int j = threadIdx.x;  // 0..63
    int beg = g_rowoff[node], end = g_rowoff[node + 1];
    float4 acc = make_float4(0.f, 0.f, 0.f, 0.f);
    for (int e = beg; e < end; e++) {
        int s = g_adj[e];
        float4 v = *(const float4*)&g_h[(size_t)s * FDIM + j * 4];
        acc.x += v.x; acc.y += v.y; acc.z += v.z; acc.w += v.w;
    }
    int d = end - beg;
    float inv = 1.0f / (float)(d > 1 ? d : 1);
    float4 hv = *(const float4*)&g_h[(size_t)node * FDIM + j * 4];
    *(float4*)&g_hcat[(size_t)node * (2 * FDIM) + j * 4] = hv;
    float4 o = make_float4(acc.x * inv, acc.y * inv, acc.z * inv, acc.w * inv);
    *(float4*)&g_hcat[(size_t)node * (2 * FDIM) + FDIM + j * 4] = o;
}

// ---------------------------------------------------------------------------
// Generic fp32 SGEMM: C[M,N] = act(A[M,K] @ W[N,K]^T + bias) (+ addsrc)
// BM=BN=128, BK=8, 256 threads, 8x8 per thread.
#define BM 128
#define BN 128
#define BK 8

__global__ __launch_bounds__(256)
void gemm_kernel(const float* __restrict__ A, int lda,
                 const int* __restrict__ gidx,
                 const float* __restrict__ W,
                 const float* __restrict__ bias,
                 const float* __restrict__ addsrc,
                 float* __restrict__ C, int ldc,
                 int M, int N, int K, int act)
{
    __shared__ float As[BK][BM];
    __shared__ float Bs[BK][BN];
    int tid = threadIdx.x;
    int bm = blockIdx.x * BM, bn = blockIdx.y * BN;
    int tx = tid & 15, ty = tid >> 4;

    int aRow = tid >> 1;
    int aK = (tid & 1) * 4;
    const float* aPtr = nullptr;
    if (bm + aRow < M) {
        int r = gidx ? gidx[bm + aRow] : (bm + aRow);
        aPtr = A + (size_t)r * lda;
    }
    const float* wPtr = (bn + aRow < N) ? (W + (size_t)(bn + aRow) * K) : nullptr;

    float acc[8][8];
    #pragma unroll
    for (int i = 0; i < 8; i++)
        #pragma unroll
        for (int j = 0; j < 8; j++) acc[i][j] = 0.f;

    for (int k0 = 0; k0 < K; k0 += BK) {
        #pragma unroll
        for (int j = 0; j < 4; j++) {
            int k = k0 + aK + j;
            As[aK + j][aRow] = (aPtr && k < K) ? aPtr[k] : 0.f;
            Bs[aK + j][aRow] = (wPtr && k < K) ? wPtr[k] : 0.f;
        }
        __syncthreads();
        #pragma unroll
        for (int kk = 0; kk < BK; kk++) {
            float a[8], b[8];
            *(float4*)&a[0] = *(const float4*)&As[kk][ty * 8];
            *(float4*)&a[4] = *(const float4*)&As[kk][ty * 8 + 4];
            *(float4*)&b[0] = *(const float4*)&Bs[kk][tx * 8];
            *(float4*)&b[4] = *(const float4*)&Bs[kk][tx * 8 + 4];
            #pragma unroll
            for (int i = 0; i < 8; i++)
                #pragma unroll
                for (int j = 0; j < 8; j++)
                    acc[i][j] += a[i] * b[j];
        }
        __syncthreads();
    }

    #pragma unroll
    for (int i = 0; i < 8; i++) {
        int r = bm + ty * 8 + i;
        if (r >= M) continue;
        #pragma unroll
        for (int j = 0; j < 8; j++) {
            int c = bn + tx * 8 + j;
            if (c >= N) continue;
            float v = acc[i][j] + bias[c];
            if (act) v = (v > 0.f) ? v : 0.1f * v;
            if (addsrc) v += addsrc[(size_t)r * ldc + c];
            C[(size_t)r * ldc + c] = v;
        }
    }
}

// ---------------------------------------------------------------------------
// L2-normalize rows (F = 256, one block of 256 threads per node)
__global__ void l2norm_kernel(const float* __restrict__ in,
                              float* __restrict__ out, int N) {
    int n = blockIdx.x;
    int t = threadIdx.x;
    float v = in[(size_t)n * FDIM + t];
    float ss = v * v;
    #pragma unroll
    for (int o = 16; o > 0; o >>= 1) ss += __shfl_xor_sync(0xffffffffu, ss, o);
    __shared__ float ws[8];
    __shared__ float s_tot;
    if ((t & 31) == 0) ws[t >> 5] = ss;
    __syncthreads();
    if (t == 0) {
        float x = 0.f;
        #pragma unroll
        for (int i = 0; i < 8; i++) x += ws[i];
        s_tot = x;
    }
    __syncthreads();
    float norm = sqrtf(s_tot);
    out[(size_t)n * FDIM + t] = v / fmaxf(norm, 1e-6f);
}

// ---------------------------------------------------------------------------
extern "C" void kernel_launch(void* const* d_in, const int* in_sizes, int n_in,
                              void* d_out, int out_size) {
    const int*   node_ids = (const int*)  d_in[0];
    const float* content  = (const float*)d_in[1];
    const int*   src      = (const int*)  d_in[2];
    const int*   dst      = (const int*)  d_in[3];
    const float* emb      = (const float*)d_in[4];
    const float* W_exp    = (const float*)d_in[5];
    const float* b_exp    = (const float*)d_in[6];
    const float* W_p1     = (const float*)d_in[7];
    const float* b_p1     = (const float*)d_in[8];
    const float* W_p2     = (const float*)d_in[9];
    const float* b_p2     = (const float*)d_in[10];
    const float* W_conv   = (const float*)d_in[11];
    const float* b_conv   = (const float*)d_in[12];
    const float* Wo1      = (const float*)d_in[13];
    const float* bo1      = (const float*)d_in[14];
    const float* Wo2      = (const float*)d_in[15];
    const float* bo2      = (const float*)d_in[16];
    float* out = (float*)d_out;

    const int N  = in_sizes[0];
    const int E  = in_sizes[2];
    const int NC = in_sizes[1] / N;                 // 300
    const int ED = in_sizes[4] / (N + 1);           // 64
    const int F  = in_sizes[5] / ED;                // 256
    const int L  = in_sizes[11] / (F * 2 * F);      // 3

    float *p_h, *p_hn, *p_tmp, *p_hcat;
    cudaGetSymbolAddress((void**)&p_h, g_h);
    cudaGetSymbolAddress((void**)&p_hn, g_hn);
    cudaGetSymbolAddress((void**)&p_tmp, g_tmp);
    cudaGetSymbolAddress((void**)&p_hcat, g_hcat);

    // ---- CSR build ----
    zero_deg_kernel<<<(N + 255) / 256, 256>>>(N);
    count_deg_kernel<<<1024, 256>>>(dst, E);
    scan_kernel<<<1, 1024>>>(N);
    scatter_kernel<<<1024, 256>>>(src, dst, E);

    dim3 gemmBlk(256);
    auto gx = [](int M) { return (M + BM - 1) / BM; };
    auto gy = [](int Nn) { return (Nn + BN - 1) / BN; };

    // ---- initial representation ----
    // h = lrelu(emb[ids] @ We^T + be)
    gemm_kernel<<<dim3(gx(N), gy(F)), gemmBlk>>>(
        emb, ED, node_ids, W_exp, b_exp, nullptr, p_h, F, N, F, ED, 1);
    // tmp = lrelu(content @ Wp1^T + bp1)
    gemm_kernel<<<dim3(gx(N), gy(NC)), gemmBlk>>>(
        content, NC, nullptr, W_p1, b_p1, nullptr, p_tmp, NC, N, NC, NC, 1);
    // h = lrelu(tmp @ Wp2^T + bp2) + h
    gemm_kernel<<<dim3(gx(N), gy(F)), gemmBlk>>>(
        p_tmp, NC, nullptr, W_p2, b_p2, p_h, p_h, F, N, F, NC, 1);

    // ---- layers ----
    for (int i = 0; i < L; i++) {
        dim3 aggBlk(64, 4);
        aggregate_kernel<<<(N + 3) / 4, aggBlk>>>(N);

        int act = (i < L - 1) ? 1 : 0;
        gemm_kernel<<<dim3(gx(N), gy(F)), gemmBlk>>>(
            p_hcat, 2 * F, nullptr,
            W_conv + (size_t)i * F * 2 * F, b_conv + (size_t)i * F,
            nullptr, p_hn, F, N, F, 2 * F, act);

        if (i < L - 1) {
            l2norm_kernel<<<N, F>>>(p_hn, p_hn, N);
            // tmp = lrelu(hn @ Wo1^T + bo1)
            gemm_kernel<<<dim3(gx(N), gy(F)), gemmBlk>>>(
                p_hn, F, nullptr,
                Wo1 + (size_t)i * F * F, bo1 + (size_t)i * F,
                nullptr, p_tmp, F, N, F, F, 1);
            // h = tmp @ Wo2^T + bo2
            gemm_kernel<<<dim3(gx(N), gy(F)), gemmBlk>>>(
                p_tmp, F, nullptr,
                Wo2 + (size_t)i * F * F, bo2 + (size_t)i * F,
                nullptr, p_h, F, N, F, F, 0);
        } else {
            l2norm_kernel<<<N, F>>>(p_hn, out, N);
        }
    }
}

// round 3
// speedup vs baseline: 2.1935x; 2.1935x over previous
#include <cuda_runtime.h>
#include <cstdint>

// ---------------------------------------------------------------------------
// GraphSage (eval) on GB300 — round 3: tf32 mma.sync GEMMs (sm_103-portable).
// ---------------------------------------------------------------------------

#define NMAX 50000
#define EMAX 1000000
#define FDIM 256

// static scratch (no allocations allowed)
__device__ __align__(16) float g_h[NMAX * FDIM];
__device__ __align__(16) float g_hn[NMAX * FDIM];
__device__ __align__(16) float g_tmp[NMAX * 304];
__device__ __align__(16) float g_hcat[NMAX * 2 * FDIM];
__device__ int g_deg[NMAX];
__device__ int g_rowoff[NMAX + 1];
__device__ int g_cursor[NMAX];
__device__ int g_adj[EMAX];

// ---------------------------------------------------------------------------
// CSR build
__global__ void zero_deg_kernel(int n) {
    int i = blockIdx.x * blockDim.x + threadIdx.x;
    if (i < n) g_deg[i] = 0;
}
__global__ void count_deg_kernel(const int* __restrict__ dst, int E) {
    int i = blockIdx.x * blockDim.x + threadIdx.x;
    int stride = gridDim.x * blockDim.x;
    for (; i < E; i += stride) atomicAdd(&g_deg[dst[i]], 1);
}
__global__ void scan_kernel(int n) {
    __shared__ int warp_sums[32];
    __shared__ int s_carry;
    int t = threadIdx.x;
    if (t == 0) s_carry = 0;
    __syncthreads();
    for (int base = 0; base < n; base += 1024) {
        int i = base + t;
        int v = (i < n) ? g_deg[i] : 0;
        int x = v;
        #pragma unroll
        for (int off = 1; off < 32; off <<= 1) {
            int y = __shfl_up_sync(0xffffffffu, x, off);
            if ((t & 31) >= off) x += y;
        }
        if ((t & 31) == 31) warp_sums[t >> 5] = x;
        __syncthreads();
        if (t < 32) {
            int w = warp_sums[t];
            int xx = w;
            #pragma unroll
            for (int off = 1; off < 32; off <<= 1) {
                int y = __shfl_up_sync(0xffffffffu, xx, off);
                if (t >= off) xx += y;
            }
            warp_sums[t] = xx - w;
        }
        __syncthreads();
        int incl = x + warp_sums[t >> 5];
        int excl = incl - v + s_carry;
        if (i < n) { g_rowoff[i] = excl; g_cursor[i] = excl; }
        __syncthreads();
        if (t == 1023) s_carry += incl;
        __syncthreads();
    }
    if (t == 0) g_rowoff[n] = s_carry;
}
__global__ void scatter_kernel(const int* __restrict__ src,
                               const int* __restrict__ dst, int E) {
    int i = blockIdx.x * blockDim.x + threadIdx.x;
    int stride = gridDim.x * blockDim.x;
    for (; i < E; i += stride) {
        int p = atomicAdd(&g_cursor[dst[i]], 1);
        g_adj[p] = src[i];
    }
}

// aggregate: hcat[n,0:256]=h[n]; hcat[n,256:512]=mean of in-neighbor h
__global__ void aggregate_kernel(int N) {
    int node = blockIdx.x * blockDim.y + threadIdx.y;
    if (node >= N) return;
    int j = threadIdx.x;  // 0..63
    int beg = g_rowoff[node], end = g_rowoff[node + 1];
    float4 acc = make_float4(0.f, 0.f, 0.f, 0.f);
    for (int e = beg; e < end; e++) {
        int s = g_adj[e];
        float4 v = *(const float4*)&g_h[(size_t)s * FDIM + j * 4];
        acc.x += v.x; acc.y += v.y; acc.z += v.z; acc.w += v.w;
    }
    int d = end - beg;
    float inv = 1.0f / (float)(d > 1 ? d : 1);
    float4 hv = *(const float4*)&g_h[(size_t)node * FDIM + j * 4];
    *(float4*)&g_hcat[(size_t)node * (2 * FDIM) + j * 4] = hv;
    float4 o = make_float4(acc.x * inv, acc.y * inv, acc.z * inv, acc.w * inv);
    *(float4*)&g_hcat[(size_t)node * (2 * FDIM) + FDIM + j * 4] = o;
}

// L2-normalize rows (F = 256)
__global__ void l2norm_kernel(const float* __restrict__ in,
                              float* __restrict__ out, int N) {
    int n = blockIdx.x;
    int t = threadIdx.x;
    float v = in[(size_t)n * FDIM + t];
    float ss = v * v;
    #pragma unroll
    for (int o = 16; o > 0; o >>= 1) ss += __shfl_xor_sync(0xffffffffu, ss, o);
    __shared__ float ws[8];
    __shared__ float s_tot;
    if ((t & 31) == 0) ws[t >> 5] = ss;
    __syncthreads();
    if (t == 0) {
        float x = 0.f;
        #pragma unroll
        for (int i = 0; i < 8; i++) x += ws[i];
        s_tot = x;
    }
    __syncthreads();
    float norm = sqrtf(s_tot);
    out[(size_t)n * FDIM + t] = v / fmaxf(norm, 1e-6f);
}

// ---------------------------------------------------------------------------
// tf32 mma.sync GEMM: C[M,Ncols] = act(A[M,K] @ W[Ncols,K]^T + bias) [+ addsrc]
// CTA tile 128x128, BK=16, 256 threads (8 warps, 2x4), warp tile 64x32.
// Smem layout: row stride 20 floats; k within a row permuted so that (k, k+4)
// are adjacent -> all fragment loads are conflict-free lds.64.
//   pos(k) = (k/8)*8 + 2*(k%4) + ((k/4)&1)

__device__ __forceinline__ uint32_t f2tf32(float x) {
    uint32_t r;
    asm("cvt.rna.tf32.f32 %0, %1;" : "=r"(r) : "f"(x));
    return r;
}
__device__ __forceinline__ void mma_tf32(float* c, const uint32_t* a,
                                         const uint32_t* b) {
    asm volatile(
        "mma.sync.aligned.m16n8k8.row.col.f32.tf32.tf32.f32 "
        "{%0,%1,%2,%3}, {%4,%5,%6,%7}, {%8,%9}, {%0,%1,%2,%3};"
        : "+f"(c[0]), "+f"(c[1]), "+f"(c[2]), "+f"(c[3])
        : "r"(a[0]), "r"(a[1]), "r"(a[2]), "r"(a[3]), "r"(b[0]), "r"(b[1]));
}

#define GBM 128
#define GBN 128
#define GBK 16
#define GSTRIDE 20

__global__ __launch_bounds__(256)
void gemm_mma(const float* __restrict__ A, int lda,
              const int* __restrict__ gidx,
              const float* __restrict__ W,
              const float* __restrict__ bias,
              const float* __restrict__ addsrc,
              float* __restrict__ C, int ldc,
              int M, int Ncols, int K, int act)
{
    __shared__ __align__(16) uint32_t As[GBM * GSTRIDE];
    __shared__ __align__(16) uint32_t Bs[GBN * GSTRIDE];

    const int tid = threadIdx.x;
    const int wid = tid >> 5;
    const int lane = tid & 31;
    const int bm = blockIdx.x * GBM;
    const int bn = blockIdx.y * GBN;

    const int warp_m = (wid >> 2) * 64;   // 0 or 64
    const int warp_n = (wid & 3) * 32;    // 0,32,64,96

    // loader roles: thread -> one row, one 8-k half
    const int ldRow = tid >> 1;
    const int kHalf = tid & 1;            // k-local base = kHalf*8

    const float* aBase = nullptr;
    if (bm + ldRow < M) {
        int r = gidx ? __ldg(&gidx[bm + ldRow]) : (bm + ldRow);
        aBase = A + (size_t)r * lda;
    }
    const float* bBase =
        (bn + ldRow < Ncols) ? (W + (size_t)(bn + ldRow) * K) : nullptr;

    const int nCh = (K + GBK - 1) / GBK;

    float acc[4][4][4];
    #pragma unroll
    for (int mt = 0; mt < 4; mt++)
        #pragma unroll
        for (int nt = 0; nt < 4; nt++)
            #pragma unroll
            for (int j = 0; j < 4; j++) acc[mt][nt][j] = 0.f;

    uint32_t ra[8], rb[8];

    // --- load one 8-k slab for a row into regs (tf32-converted) ---
    auto loadSlab = [&](const float* base, int k0, uint32_t* r) {
        if (base && k0 + 8 <= K) {
            float4 v0 = *(const float4*)(base + k0);
            float4 v1 = *(const float4*)(base + k0 + 4);
            r[0] = f2tf32(v0.x); r[1] = f2tf32(v0.y);
            r[2] = f2tf32(v0.z); r[3] = f2tf32(v0.w);
            r[4] = f2tf32(v1.x); r[5] = f2tf32(v1.y);
            r[6] = f2tf32(v1.z); r[7] = f2tf32(v1.w);
        } else {
            #pragma unroll
            for (int j = 0; j < 8; j++) {
                float v = (base && (k0 + j) < K) ? base[k0 + j] : 0.f;
                r[j] = f2tf32(v);
            }
        }
    };
    // permuted store: slab j=0..7 (k = j) -> pos 0,2,4,6,1,3,5,7
    auto storeSlab = [&](uint32_t* sm, const uint32_t* r) {
        uint32_t* d = sm + ldRow * GSTRIDE + kHalf * 8;
        d[0] = r[0]; d[2] = r[1]; d[4] = r[2]; d[6] = r[3];
        d[1] = r[4]; d[3] = r[5]; d[5] = r[6]; d[7] = r[7];
    };

    auto computeTile = [&]() {
        #pragma unroll
        for (int s = 0; s < 2; s++) {
            uint32_t af[4][4], bf[4][2];
            const int kcol = s * 8 + 2 * (lane & 3);
            #pragma unroll
            for (int mt = 0; mt < 4; mt++) {
                int r0 = warp_m + mt * 16 + (lane >> 2);
                uint2 lo = *(const uint2*)&As[r0 * GSTRIDE + kcol];
                uint2 hi = *(const uint2*)&As[(r0 + 8) * GSTRIDE + kcol];
                af[mt][0] = lo.x; af[mt][1] = hi.x;
                af[mt][2] = lo.y; af[mt][3] = hi.y;
            }
            #pragma unroll
            for (int nt = 0; nt < 4; nt++) {
                int n0 = warp_n + nt * 8 + (lane >> 2);
                uint2 b = *(const uint2*)&Bs[n0 * GSTRIDE + kcol];
                bf[nt][0] = b.x; bf[nt][1] = b.y;
            }
            #pragma unroll
            for (int mt = 0; mt < 4; mt++)
                #pragma unroll
                for (int nt = 0; nt < 4; nt++)
                    mma_tf32(acc[mt][nt], af[mt], bf[nt]);
        }
    };

    // pipeline: prefetch chunk ch+1 into regs while computing chunk ch
    loadSlab(aBase, kHalf * 8, ra);
    loadSlab(bBase, kHalf * 8, rb);
    storeSlab(As, ra);
    storeSlab(Bs, rb);
    __syncthreads();
    for (int ch = 1; ch < nCh; ch++) {
        int k0 = ch * GBK + kHalf * 8;
        loadSlab(aBase, k0, ra);
        loadSlab(bBase, k0, rb);
        computeTile();
        __syncthreads();
        storeSlab(As, ra);
        storeSlab(Bs, rb);
        __syncthreads();
    }
    computeTile();

    // ---- epilogue ----
    #pragma unroll
    for (int mt = 0; mt < 4; mt++) {
        int row = bm + warp_m + mt * 16 + (lane >> 2);
        #pragma unroll
        for (int nt = 0; nt < 4; nt++) {
            int col = bn + warp_n + nt * 8 + 2 * (lane & 3);
            if (col >= Ncols) continue;  // Ncols even -> col+1 also valid
            float b0 = __ldg(&bias[col]);
            float b1 = __ldg(&bias[col + 1]);
            #pragma unroll
            for (int half = 0; half < 2; half++) {
                int r = row + half * 8;
                if (r >= M) continue;
                float v0 = acc[mt][nt][half * 2 + 0] + b0;
                float v1 = acc[mt][nt][half * 2 + 1] + b1;
                if (act) {
                    v0 = (v0 > 0.f) ? v0 : 0.1f * v0;
                    v1 = (v1 > 0.f) ? v1 : 0.1f * v1;
                }
                if (addsrc) {
                    const float2 s = *(const float2*)&addsrc[(size_t)r * ldc + col];
                    v0 += s.x; v1 += s.y;
                }
                *(float2*)&C[(size_t)r * ldc + col] = make_float2(v0, v1);
            }
        }
    }
}

// ---------------------------------------------------------------------------
extern "C" void kernel_launch(void* const* d_in, const int* in_sizes, int n_in,
                              void* d_out, int out_size) {
    const int*   node_ids = (const int*)  d_in[0];
    const float* content  = (const float*)d_in[1];
    const int*   src      = (const int*)  d_in[2];
    const int*   dst      = (const int*)  d_in[3];
    const float* emb      = (const float*)d_in[4];
    const float* W_exp    = (const float*)d_in[5];
    const float* b_exp    = (const float*)d_in[6];
    const float* W_p1     = (const float*)d_in[7];
    const float* b_p1     = (const float*)d_in[8];
    const float* W_p2     = (const float*)d_in[9];
    const float* b_p2     = (const float*)d_in[10];
    const float* W_conv   = (const float*)d_in[11];
    const float* b_conv   = (const float*)d_in[12];
    const float* Wo1      = (const float*)d_in[13];
    const float* bo1      = (const float*)d_in[14];
    const float* Wo2      = (const float*)d_in[15];
    const float* bo2      = (const float*)d_in[16];
    float* out = (float*)d_out;

    const int N  = in_sizes[0];
    const int E  = in_sizes[2];
    const int NC = in_sizes[1] / N;                 // 300
    const int ED = in_sizes[4] / (N + 1);           // 64
    const int F  = in_sizes[5] / ED;                // 256
    const int L  = in_sizes[11] / (F * 2 * F);      // 3

    float *p_h, *p_hn, *p_tmp, *p_hcat;
    cudaGetSymbolAddress((void**)&p_h, g_h);
    cudaGetSymbolAddress((void**)&p_hn, g_hn);
    cudaGetSymbolAddress((void**)&p_tmp, g_tmp);
    cudaGetSymbolAddress((void**)&p_hcat, g_hcat);

    // ---- CSR build ----
    zero_deg_kernel<<<(N + 255) / 256, 256>>>(N);
    count_deg_kernel<<<1024, 256>>>(dst, E);
    scan_kernel<<<1, 1024>>>(N);
    scatter_kernel<<<1024, 256>>>(src, dst, E);

    const int gmx = (N + GBM - 1) / GBM;
    auto gy = [](int n) { return (n + GBN - 1) / GBN; };

    // ---- initial representation ----
    // h = lrelu(emb[ids] @ We^T + be)
    gemm_mma<<<dim3(gmx, gy(F)), 256>>>(
        emb, ED, node_ids, W_exp, b_exp, nullptr, p_h, F, N, F, ED, 1);
    // tmp = lrelu(content @ Wp1^T + bp1)
    gemm_mma<<<dim3(gmx, gy(NC)), 256>>>(
        content, NC, nullptr, W_p1, b_p1, nullptr, p_tmp, NC, N, NC, NC, 1);
    // h = lrelu(tmp @ Wp2^T + bp2) + h
    gemm_mma<<<dim3(gmx, gy(F)), 256>>>(
        p_tmp, NC, nullptr, W_p2, b_p2, p_h, p_h, F, N, F, NC, 1);

    // ---- layers ----
    for (int i = 0; i < L; i++) {
        dim3 aggBlk(64, 4);
        aggregate_kernel<<<(N + 3) / 4, aggBlk>>>(N);

        int act = (i < L - 1) ? 1 : 0;
        gemm_mma<<<dim3(gmx, gy(F)), 256>>>(
            p_hcat, 2 * F, nullptr,
            W_conv + (size_t)i * F * 2 * F, b_conv + (size_t)i * F,
            nullptr, p_hn, F, N, F, 2 * F, act);

        if (i < L - 1) {
            l2norm_kernel<<<N, F>>>(p_hn, p_hn, N);
            gemm_mma<<<dim3(gmx, gy(F)), 256>>>(
                p_hn, F, nullptr,
                Wo1 + (size_t)i * F * F, bo1 + (size_t)i * F,
                nullptr, p_tmp, F, N, F, F, 1);
            gemm_mma<<<dim3(gmx, gy(F)), 256>>>(
                p_tmp, F, nullptr,
                Wo2 + (size_t)i * F * F, bo2 + (size_t)i * F,
                nullptr, p_h, F, N, F, F, 0);
        } else {
            l2norm_kernel<<<N, F>>>(p_hn, out, N);
        }
    }
}

// round 4
// speedup vs baseline: 2.7429x; 1.2505x over previous
#include <cuda_runtime.h>
#include <cstdint>

// ---------------------------------------------------------------------------
// GraphSage (eval) on GB300 — round 4: cp.async 3-stage tf32 mma.sync GEMM.
// ---------------------------------------------------------------------------

#define NMAX 50000
#define EMAX 1000000
#define FDIM 256

__device__ __align__(16) float g_h[NMAX * FDIM];
__device__ __align__(16) float g_hn[NMAX * FDIM];
__device__ __align__(16) float g_tmp[NMAX * 304];
__device__ __align__(16) float g_hcat[NMAX * 2 * FDIM];
__device__ int g_deg[NMAX];
__device__ int g_rowoff[NMAX + 1];
__device__ int g_cursor[NMAX];
__device__ int g_adj[EMAX];

// ---------------------------------------------------------------------------
// CSR build
__global__ void zero_deg_kernel(int n) {
    int i = blockIdx.x * blockDim.x + threadIdx.x;
    if (i < n) g_deg[i] = 0;
}
__global__ void count_deg_kernel(const int* __restrict__ dst, int E) {
    int i = blockIdx.x * blockDim.x + threadIdx.x;
    int stride = gridDim.x * blockDim.x;
    for (; i < E; i += stride) atomicAdd(&g_deg[dst[i]], 1);
}
__global__ void scan_kernel(int n) {
    __shared__ int warp_sums[32];
    __shared__ int s_carry;
    int t = threadIdx.x;
    if (t == 0) s_carry = 0;
    __syncthreads();
    for (int base = 0; base < n; base += 1024) {
        int i = base + t;
        int v = (i < n) ? g_deg[i] : 0;
        int x = v;
        #pragma unroll
        for (int off = 1; off < 32; off <<= 1) {
            int y = __shfl_up_sync(0xffffffffu, x, off);
            if ((t & 31) >= off) x += y;
        }
        if ((t & 31) == 31) warp_sums[t >> 5] = x;
        __syncthreads();
        if (t < 32) {
            int w = warp_sums[t];
            int xx = w;
            #pragma unroll
            for (int off = 1; off < 32; off <<= 1) {
                int y = __shfl_up_sync(0xffffffffu, xx, off);
                if (t >= off) xx += y;
            }
            warp_sums[t] = xx - w;
        }
        __syncthreads();
        int incl = x + warp_sums[t >> 5];
        int excl = incl - v + s_carry;
        if (i < n) { g_rowoff[i] = excl; g_cursor[i] = excl; }
        __syncthreads();
        if (t == 1023) s_carry += incl;
        __syncthreads();
    }
    if (t == 0) g_rowoff[n] = s_carry;
}
__global__ void scatter_kernel(const int* __restrict__ src,
                               const int* __restrict__ dst, int E) {
    int i = blockIdx.x * blockDim.x + threadIdx.x;
    int stride = gridDim.x * blockDim.x;
    for (; i < E; i += stride) {
        int p = atomicAdd(&g_cursor[dst[i]], 1);
        g_adj[p] = src[i];
    }
}

// aggregate: hcat[n,0:256]=h[n]; hcat[n,256:512]=mean of in-neighbor h
__global__ void aggregate_kernel(int N) {
    int node = blockIdx.x * blockDim.y + threadIdx.y;
    if (node >= N) return;
    int j = threadIdx.x;  // 0..63
    int beg = g_rowoff[node], end = g_rowoff[node + 1];
    float4 acc = make_float4(0.f, 0.f, 0.f, 0.f);
    for (int e = beg; e < end; e++) {
        int s = g_adj[e];
        float4 v = *(const float4*)&g_h[(size_t)s * FDIM + j * 4];
        acc.x += v.x; acc.y += v.y; acc.z += v.z; acc.w += v.w;
    }
    int d = end - beg;
    float inv = 1.0f / (float)(d > 1 ? d : 1);
    float4 hv = *(const float4*)&g_h[(size_t)node * FDIM + j * 4];
    *(float4*)&g_hcat[(size_t)node * (2 * FDIM) + j * 4] = hv;
    float4 o = make_float4(acc.x * inv, acc.y * inv, acc.z * inv, acc.w * inv);
    *(float4*)&g_hcat[(size_t)node * (2 * FDIM) + FDIM + j * 4] = o;
}

// L2-normalize rows (F = 256)
__global__ void l2norm_kernel(const float* __restrict__ in,
                              float* __restrict__ out, int N) {
    int n = blockIdx.x;
    int t = threadIdx.x;
    float v = in[(size_t)n * FDIM + t];
    float ss = v * v;
    #pragma unroll
    for (int o = 16; o > 0; o >>= 1) ss += __shfl_xor_sync(0xffffffffu, ss, o);
    __shared__ float ws[8];
    __shared__ float s_tot;
    if ((t & 31) == 0) ws[t >> 5] = ss;
    __syncthreads();
    if (t == 0) {
        float x = 0.f;
        #pragma unroll
        for (int i = 0; i < 8; i++) x += ws[i];
        s_tot = x;
    }
    __syncthreads();
    float norm = sqrtf(s_tot);
    out[(size_t)n * FDIM + t] = v / fmaxf(norm, 1e-6f);
}

// ---------------------------------------------------------------------------
// tf32 mma.sync GEMM with cp.async 3-stage pipeline.
// C[M,Ncols] = act(A[M,K] @ W[Ncols,K]^T + bias) [+ addsrc]
// CTA 128x128, K-chunk 32, 256 threads (8 warps 2x4), warp tile 64x32.
// Smem: per stage A[128][36] + B[128][36] fp32 (pad 4 -> conflict-free lds.32).

__device__ __forceinline__ uint32_t f2tf32(float x) {
    uint32_t r;
    asm("cvt.rna.tf32.f32 %0, %1;" : "=r"(r) : "f"(x));
    return r;
}
__device__ __forceinline__ void mma_tf32(float* c, const uint32_t* a,
                                         const uint32_t* b) {
    asm volatile(
        "mma.sync.aligned.m16n8k8.row.col.f32.tf32.tf32.f32 "
        "{%0,%1,%2,%3}, {%4,%5,%6,%7}, {%8,%9}, {%0,%1,%2,%3};"
        : "+f"(c[0]), "+f"(c[1]), "+f"(c[2]), "+f"(c[3])
        : "r"(a[0]), "r"(a[1]), "r"(a[2]), "r"(a[3]), "r"(b[0]), "r"(b[1]));
}
__device__ __forceinline__ void cp16(uint32_t dst, const void* src, int nbytes) {
    asm volatile("cp.async.cg.shared.global [%0], [%1], 16, %2;"
                 :: "r"(dst), "l"(src), "r"(nbytes) : "memory");
}
__device__ __forceinline__ void cp_commit() {
    asm volatile("cp.async.commit_group;" ::: "memory");
}
__device__ __forceinline__ void cp_wait1() {
    asm volatile("cp.async.wait_group 1;" ::: "memory");
}

#define GBM 128
#define GBN 128
#define GBK 32
#define GST 36                       // floats per smem row
#define SFLOATS (128 * GST)          // one matrix, one stage
#define STAGE_FLOATS (2 * SFLOATS)   // A + B
#define NSTAGE 3

extern __shared__ float sm_dyn[];

__global__ __launch_bounds__(256, 2)
void gemm_mma(const float* __restrict__ A, int lda,
              const int* __restrict__ gidx,
              const float* __restrict__ W,
              const float* __restrict__ bias,
              const float* __restrict__ addsrc,
              float* __restrict__ C, int ldc,
              int M, int Ncols, int K, int act)
{
    const int tid = threadIdx.x;
    const int wid = tid >> 5;
    const int lane = tid & 31;
    const int bm = blockIdx.x * GBM;
    const int bn = blockIdx.y * GBN;
    const int warp_m = (wid >> 2) * 64;
    const int warp_n = (wid & 3) * 32;

    // loader role: row = tid>>1, 16-float half = tid&1
    const int ldRow = tid >> 1;
    const int kHalf = tid & 1;

    const bool aValid = (bm + ldRow < M);
    int aR = aValid ? (bm + ldRow) : 0;
    if (gidx) aR = __ldg(&gidx[aValid ? bm + ldRow : 0]);
    const float* aBase = A + (size_t)aR * lda;
    const bool bValid = (bn + ldRow < Ncols);
    const float* bBase = W + (size_t)(bValid ? bn + ldRow : 0) * K;

    const uint32_t smemBase = (uint32_t)__cvta_generic_to_shared(sm_dyn);

    const int nCh = (K + GBK - 1) / GBK;

    float acc[4][4][4];
    #pragma unroll
    for (int mt = 0; mt < 4; mt++)
        #pragma unroll
        for (int nt = 0; nt < 4; nt++)
            #pragma unroll
            for (int j = 0; j < 4; j++) acc[mt][nt][j] = 0.f;

    // ---- issue one stage's cp.asyncs (always commits a group) ----
    auto issueStage = [&](int ch, int stage) {
        if (ch < nCh) {
            const int k0 = ch * GBK + kHalf * 16;
            const uint32_t dRow =
                smemBase + (stage * STAGE_FLOATS + ldRow * GST + kHalf * 16) * 4;
            const uint32_t dRowB = dRow + SFLOATS * 4;
            #pragma unroll
            for (int j = 0; j < 4; j++) {
                const int c = k0 + j * 4;
                const int rem = K - c;
                const int nbF = (rem >= 4) ? 16 : (rem > 0 ? rem * 4 : 0);
                cp16(dRow + j * 16, aBase + c, aValid ? nbF : 0);
                cp16(dRowB + j * 16, bBase + c, bValid ? nbF : 0);
            }
        }
        cp_commit();
    };

    auto computeStage = [&](int stage) {
        const float* As = sm_dyn + stage * STAGE_FLOATS;
        const float* Bs = As + SFLOATS;
        #pragma unroll
        for (int p = 0; p < 4; p++) {
            const int kc = p * 8 + (lane & 3);
            uint32_t af[4][4], bf[4][2];
            #pragma unroll
            for (int mt = 0; mt < 4; mt++) {
                const int r0 = warp_m + mt * 16 + (lane >> 2);
                af[mt][0] = f2tf32(As[r0 * GST + kc]);
                af[mt][1] = f2tf32(As[(r0 + 8) * GST + kc]);
                af[mt][2] = f2tf32(As[r0 * GST + kc + 4]);
                af[mt][3] = f2tf32(As[(r0 + 8) * GST + kc + 4]);
            }
            #pragma unroll
            for (int nt = 0; nt < 4; nt++) {
                const int c0 = warp_n + nt * 8 + (lane >> 2);
                bf[nt][0] = f2tf32(Bs[c0 * GST + kc]);
                bf[nt][1] = f2tf32(Bs[c0 * GST + kc + 4]);
            }
            #pragma unroll
            for (int mt = 0; mt < 4; mt++)
                #pragma unroll
                for (int nt = 0; nt < 4; nt++)
                    mma_tf32(acc[mt][nt], af[mt], bf[nt]);
        }
    };

    // ---- pipeline ----
    issueStage(0, 0);
    issueStage(1, 1);
    for (int ch = 0; ch < nCh; ch++) {
        cp_wait1();
        __syncthreads();
        computeStage(ch % NSTAGE);
        issueStage(ch + 2, (ch + 2) % NSTAGE);
    }

    // ---- epilogue ----
    #pragma unroll
    for (int mt = 0; mt < 4; mt++) {
        int row = bm + warp_m + mt * 16 + (lane >> 2);
        #pragma unroll
        for (int nt = 0; nt < 4; nt++) {
            int col = bn + warp_n + nt * 8 + 2 * (lane & 3);
            if (col >= Ncols) continue;
            float b0 = __ldg(&bias[col]);
            float b1 = __ldg(&bias[col + 1]);
            #pragma unroll
            for (int half = 0; half < 2; half++) {
                int r = row + half * 8;
                if (r >= M) continue;
                float v0 = acc[mt][nt][half * 2 + 0] + b0;
                float v1 = acc[mt][nt][half * 2 + 1] + b1;
                if (act) {
                    v0 = (v0 > 0.f) ? v0 : 0.1f * v0;
                    v1 = (v1 > 0.f) ? v1 : 0.1f * v1;
                }
                if (addsrc) {
                    const float2 s = *(const float2*)&addsrc[(size_t)r * ldc + col];
                    v0 += s.x; v1 += s.y;
                }
                *(float2*)&C[(size_t)r * ldc + col] = make_float2(v0, v1);
            }
        }
    }
}

// ---------------------------------------------------------------------------
extern "C" void kernel_launch(void* const* d_in, const int* in_sizes, int n_in,
                              void* d_out, int out_size) {
    const int*   node_ids = (const int*)  d_in[0];
    const float* content  = (const float*)d_in[1];
    const int*   src      = (const int*)  d_in[2];
    const int*   dst      = (const int*)  d_in[3];
    const float* emb      = (const float*)d_in[4];
    const float* W_exp    = (const float*)d_in[5];
    const float* b_exp    = (const float*)d_in[6];
    const float* W_p1     = (const float*)d_in[7];
    const float* b_p1     = (const float*)d_in[8];
    const float* W_p2     = (const float*)d_in[9];
    const float* b_p2     = (const float*)d_in[10];
    const float* W_conv   = (const float*)d_in[11];
    const float* b_conv   = (const float*)d_in[12];
    const float* Wo1      = (const float*)d_in[13];
    const float* bo1      = (const float*)d_in[14];
    const float* Wo2      = (const float*)d_in[15];
    const float* bo2      = (const float*)d_in[16];
    float* out = (float*)d_out;

    const int N  = in_sizes[0];
    const int E  = in_sizes[2];
    const int NC = in_sizes[1] / N;                 // 300
    const int ED = in_sizes[4] / (N + 1);           // 64
    const int F  = in_sizes[5] / ED;                // 256
    const int L  = in_sizes[11] / (F * 2 * F);      // 3

    float *p_h, *p_hn, *p_tmp, *p_hcat;
    cudaGetSymbolAddress((void**)&p_h, g_h);
    cudaGetSymbolAddress((void**)&p_hn, g_hn);
    cudaGetSymbolAddress((void**)&p_tmp, g_tmp);
    cudaGetSymbolAddress((void**)&p_hcat, g_hcat);

    const int SMEM = NSTAGE * STAGE_FLOATS * 4;  // 110592 B
    cudaFuncSetAttribute(gemm_mma, cudaFuncAttributeMaxDynamicSharedMemorySize, SMEM);

    // ---- CSR build ----
    zero_deg_kernel<<<(N + 255) / 256, 256>>>(N);
    count_deg_kernel<<<1024, 256>>>(dst, E);
    scan_kernel<<<1, 1024>>>(N);
    scatter_kernel<<<1024, 256>>>(src, dst, E);

    const int gmx = (N + GBM - 1) / GBM;
    auto gy = [](int n) { return (n + GBN - 1) / GBN; };

    // ---- initial representation ----
    gemm_mma<<<dim3(gmx, gy(F)), 256, SMEM>>>(
        emb, ED, node_ids, W_exp, b_exp, nullptr, p_h, F, N, F, ED, 1);
    gemm_mma<<<dim3(gmx, gy(NC)), 256, SMEM>>>(
        content, NC, nullptr, W_p1, b_p1, nullptr, p_tmp, NC, N, NC, NC, 1);
    gemm_mma<<<dim3(gmx, gy(F)), 256, SMEM>>>(
        p_tmp, NC, nullptr, W_p2, b_p2, p_h, p_h, F, N, F, NC, 1);

    // ---- layers ----
    for (int i = 0; i < L; i++) {
        dim3 aggBlk(64, 4);
        aggregate_kernel<<<(N + 3) / 4, aggBlk>>>(N);

        int act = (i < L - 1) ? 1 : 0;
        gemm_mma<<<dim3(gmx, gy(F)), 256, SMEM>>>(
            p_hcat, 2 * F, nullptr,
            W_conv + (size_t)i * F * 2 * F, b_conv + (size_t)i * F,
            nullptr, p_hn, F, N, F, 2 * F, act);

        if (i < L - 1) {
            l2norm_kernel<<<N, F>>>(p_hn, p_hn, N);
            gemm_mma<<<dim3(gmx, gy(F)), 256, SMEM>>>(
                p_hn, F, nullptr,
                Wo1 + (size_t)i * F * F, bo1 + (size_t)i * F,
                nullptr, p_tmp, F, N, F, F, 1);
            gemm_mma<<<dim3(gmx, gy(F)), 256, SMEM>>>(
                p_tmp, F, nullptr,
                Wo2 + (size_t)i * F * F, bo2 + (size_t)i * F,
                nullptr, p_h, F, N, F, F, 0);
        } else {
            l2norm_kernel<<<N, F>>>(p_hn, out, N);
        }
    }
}